// round 11
// baseline (speedup 1.0000x reference)
#include <cuda_runtime.h>
#include <math.h>

#define NC 23
#define NG 20000
#define NN 64
#define NH 64

#define BLKA 256
#define NBLKA ((NG + BLKA - 1) / BLKA)   // 79

#define BLK 256
#define WARPS (BLK / 32)
#define CHUNKS 9                         // gene chunks per batch row
#define GPC ((NG + CHUNKS - 1) / CHUNKS) // 2223
#define GRIDMAIN (NN * CHUNKS)           // 576 blocks = one full wave

// ---- scratch (static device globals; no allocation in kernel_launch) ----
__device__ int   d_assign[NG];
__device__ float d_outacc[NN * NC * NH];
__device__ float d_sumw[NN * NC];

// ---------------- P1: per-gene assignment + accumulator zeroing ------------

__global__ __launch_bounds__(BLKA)
void k_assign(const float* __restrict__ chrom) {
    const int g = blockIdx.x * BLKA + threadIdx.x;

    if (g < NG) {
        int ci = 0;
        #pragma unroll
        for (int c = 0; c < NC; c++) {
            float v = chrom[c * NG + g];       // coalesced across g
            if (v != 0.f) ci = c;              // one-hot: exactly one hit
        }
        d_assign[g] = ci;
    }

    const int nt = NBLKA * BLKA;
    for (int i = g; i < NN * NC * NH; i += nt)
        d_outacc[i] = 0.f;
    if (g < NN * NC)
        d_sumw[g] = 0.f;
}

// ---------------- main pass: sequential x streaming -------------------------
// Each block: one batch n, one contiguous gene chunk. Warps take genes
// round-robin (full-warp 256B rows, perfectly coalesced & sequential).
// Per-warp private smem accumulators [NC][NH] -> no atomics in the hot loop.

__device__ __forceinline__ float gene_weight(float s) {
    float w = 0.f;
    if (s != 0.f) {
        float lr = s > 0.f ? s : 0.2f * s;   // leaky_relu(0.2)
        w = __expf(lr);
    }
    return w;
}

__global__ __launch_bounds__(BLK)
void k_main(const float* __restrict__ x, const float* __restrict__ attn) {
    __shared__ float s_wacc[WARPS * NC * NH];  // 47104 B
    __shared__ float s_wsum[WARPS * NC];       //   736 B

    const int bid   = blockIdx.x;
    const int n     = bid / CHUNKS;
    const int chunk = bid % CHUNKS;
    const int g0 = chunk * GPC;
    const int g1 = min(g0 + GPC, NG);

    const int tid  = threadIdx.x;
    const int wid  = tid >> 5;
    const int lane = tid & 31;

    for (int i = tid; i < WARPS * NC * NH; i += BLK) s_wacc[i] = 0.f;
    for (int i = tid; i < WARPS * NC; i += BLK)      s_wsum[i] = 0.f;
    __syncthreads();

    const float* xb = x + (long long)n * NG * NH;
    float* wacc = s_wacc + wid * NC * NH;
    float* wsum = s_wsum + wid * NC;

    int g = g0 + wid;

    // 2-way unrolled: two independent load+reduce chains per warp
    for (; g + WARPS < g1; g += 2 * WARPS) {
        const int ga = g;
        const int gb = g + WARPS;
        const int ci0 = d_assign[ga];
        const int ci1 = d_assign[gb];
        const float2 xv0 = *reinterpret_cast<const float2*>(
            xb + (long long)ga * NH + 2 * lane);
        const float2 xv1 = *reinterpret_cast<const float2*>(
            xb + (long long)gb * NH + 2 * lane);
        const float2 a0 = *reinterpret_cast<const float2*>(
            attn + ci0 * NH + 2 * lane);
        const float2 a1 = *reinterpret_cast<const float2*>(
            attn + ci1 * NH + 2 * lane);

        float s0 = a0.x * xv0.x + a0.y * xv0.y;
        float s1 = a1.x * xv1.x + a1.y * xv1.y;
        #pragma unroll
        for (int d = 16; d > 0; d >>= 1) {
            s0 += __shfl_xor_sync(0xffffffffu, s0, d);
            s1 += __shfl_xor_sync(0xffffffffu, s1, d);
        }
        const float w0 = gene_weight(s0);
        const float w1 = gene_weight(s1);

        float2* p0 = reinterpret_cast<float2*>(wacc + ci0 * NH + 2 * lane);
        float2 c0 = *p0;
        c0.x += w0 * xv0.x; c0.y += w0 * xv0.y;
        *p0 = c0;
        float2* p1 = reinterpret_cast<float2*>(wacc + ci1 * NH + 2 * lane);
        float2 c1 = *p1;
        c1.x += w1 * xv1.x; c1.y += w1 * xv1.y;
        *p1 = c1;

        if (lane == 0) {
            wsum[ci0] += w0;
            wsum[ci1] += w1;
        }
    }
    for (; g < g1; g += WARPS) {
        const int ci = d_assign[g];
        const float2 xv = *reinterpret_cast<const float2*>(
            xb + (long long)g * NH + 2 * lane);
        const float2 a = *reinterpret_cast<const float2*>(
            attn + ci * NH + 2 * lane);
        float s = a.x * xv.x + a.y * xv.y;
        #pragma unroll
        for (int d = 16; d > 0; d >>= 1)
            s += __shfl_xor_sync(0xffffffffu, s, d);
        const float w = gene_weight(s);
        float2* p = reinterpret_cast<float2*>(wacc + ci * NH + 2 * lane);
        float2 c = *p;
        c.x += w * xv.x; c.y += w * xv.y;
        *p = c;
        if (lane == 0) wsum[ci] += w;
    }
    __syncthreads();

    // cross-warp reduce + global accumulation (spread-address REDG)
    for (int i = tid; i < NC * NH; i += BLK) {
        float s = 0.f;
        #pragma unroll
        for (int w = 0; w < WARPS; w++) s += s_wacc[w * NC * NH + i];
        atomicAdd(&d_outacc[n * NC * NH + i], s);
    }
    for (int i = tid; i < NC; i += BLK) {
        float s = 0.f;
        #pragma unroll
        for (int w = 0; w < WARPS; w++) s += s_wsum[w * NC + i];
        atomicAdd(&d_sumw[n * NC + i], s);
    }
}

// ---------------- epilogue --------------------------------------------------

__global__ void k_final(float4* __restrict__ out) {
    int t = blockIdx.x * blockDim.x + threadIdx.x;   // float4 index
    if (t < NN * NC * NH / 4) {
        int ni = t / (NH / 4);
        float s = fmaxf(d_sumw[ni], 1e-10f);
        float4 v = reinterpret_cast<const float4*>(d_outacc)[t];
        v.x /= s; v.y /= s; v.z /= s; v.w /= s;
        out[t] = v;
    }
}

// ---------------- launcher --------------------------------------------------

extern "C" void kernel_launch(void* const* d_in, const int* in_sizes, int n_in,
                              void* d_out, int out_size) {
    const float* x     = (const float*)d_in[0];   // (N, G, H)
    const float* chrom = (const float*)d_in[1];   // (C, G)
    const float* attn  = (const float*)d_in[2];   // (C, H)
    float4* out = (float4*)d_out;                 // (N, C, H)

    (void)in_sizes; (void)n_in; (void)out_size;

    // per-gene chromosome assignment + accumulator zeroing (no bucketing!)
    k_assign<<<NBLKA, BLKA>>>(chrom);

    // sequential-streaming fused pass
    k_main<<<GRIDMAIN, BLK>>>(x, attn);

    // normalize
    const int nf4 = NN * NC * NH / 4;
    k_final<<<(nf4 + BLK - 1) / BLK, BLK>>>(out);
}

// round 12
// speedup vs baseline: 1.0576x; 1.0576x over previous
#include <cuda_runtime.h>
#include <cuda_pipeline.h>
#include <math.h>

#define NC 23
#define NG 20000
#define NN 64
#define NH 64

#define BLKA 256
#define NBLKA ((NG + BLKA - 1) / BLKA)   // 79

#define CHUNKS 6
#define GPC ((NG + CHUNKS - 1) / CHUNKS) // 3334
#define TILE 128
#define BLK 128
#define WARPS (BLK / 32)                 // 4

// dynamic smem layout (bytes)
#define SM_TILE   0
#define SM_ATTN   (TILE * 16 * 16)                   // 32768
#define SM_ACC    (SM_ATTN + NC * 16 * 16)           // 32768 + 5888 = 38656
#define SM_WSUM   (SM_ACC + WARPS * NC * NH * 4)     // + 23552 = 62208
#define SMEM_TOTAL (SM_WSUM + WARPS * NC * 4)        // + 368 = 62576

// ---- scratch (static device globals; no allocation in kernel_launch) ----
__device__ int   d_assign[NG];
__device__ float d_outacc[NN * NC * NH];
__device__ float d_sumw[NN * NC];

// ---------------- P1: per-gene assignment + accumulator zeroing ------------

__global__ __launch_bounds__(BLKA)
void k_assign(const float* __restrict__ chrom) {
    const int g = blockIdx.x * BLKA + threadIdx.x;

    if (g < NG) {
        int ci = 0;
        #pragma unroll
        for (int c = 0; c < NC; c++) {
            float v = chrom[c * NG + g];       // coalesced across g
            if (v != 0.f) ci = c;              // one-hot: exactly one hit
        }
        d_assign[g] = ci;
    }

    const int nt = NBLKA * BLKA;
    for (int i = g; i < NN * NC * NH; i += nt)
        d_outacc[i] = 0.f;
    if (g < NN * NC)
        d_sumw[g] = 0.f;
}

// ---------------- main pass: tile-phased sequential streaming ---------------
// Block = (n, chunk). Per tile of 128 contiguous genes:
//   L : cp.async 32KB sequential stage (XOR-swizzled float4 rows)
//   C1: thread t computes full dot for gene t (no shuffles), w in register
//   C2: warp w accumulates genes of its own lanes into per-warp smem acc

__global__ __launch_bounds__(BLK)
void k_main(const float* __restrict__ x, const float* __restrict__ attn) {
    extern __shared__ char smem_raw[];
    float4* s_tile = reinterpret_cast<float4*>(smem_raw + SM_TILE);  // [128][16]
    float4* s_attn = reinterpret_cast<float4*>(smem_raw + SM_ATTN);  // [23][16]
    float*  s_acc  = reinterpret_cast<float*>(smem_raw + SM_ACC);    // [4][23][64]
    float*  s_wsum = reinterpret_cast<float*>(smem_raw + SM_WSUM);   // [4][23]

    const int n     = blockIdx.x / CHUNKS;
    const int chunk = blockIdx.x % CHUNKS;
    const int c0 = chunk * GPC;
    const int c1 = min(c0 + GPC, NG);

    const int tid  = threadIdx.x;    // 0..127
    const int wid  = tid >> 5;
    const int lane = tid & 31;

    // stage attn swizzled: attn[ci][j] -> s_attn[ci*16 + (j ^ (ci & 15))]
    for (int i = tid; i < NC * 16; i += BLK) {
        const int ci = i >> 4, j = i & 15;
        s_attn[ci * 16 + (j ^ (ci & 15))] =
            reinterpret_cast<const float4*>(attn)[ci * 16 + j];
    }
    for (int i = tid; i < WARPS * NC * NH; i += BLK) s_acc[i] = 0.f;
    for (int i = tid; i < WARPS * NC; i += BLK)      s_wsum[i] = 0.f;
    __syncthreads();

    const float* xb = x + (long long)n * NG * NH;
    float* wacc = s_acc + wid * NC * NH;
    float* wsum = s_wsum + wid * NC;

    for (int tbase = c0; tbase < c1; tbase += TILE) {
        // ---- L: sequential cp.async stage, swizzled ----
        {
            const int j  = tid & 15;           // float4 column (constant/thread)
            const int r0 = tid >> 4;           // 0..7
            #pragma unroll
            for (int k = 0; k < 16; k++) {
                const int r = r0 + (k << 3);   // tile row 0..127
                const int g = tbase + r;
                const int gs = min(g, NG - 1); // clamp (masked by w=0)
                const float4* src =
                    reinterpret_cast<const float4*>(xb + (long long)gs * NH) + j;
                float4* dst = &s_tile[r * 16 + (j ^ (r & 15))];
                __pipeline_memcpy_async(dst, src, 16);
            }
            __pipeline_commit();
        }

        // ci for this thread's gene (overlaps the async stage)
        const int myg = tbase + tid;
        int ci = 0;
        if (myg < c1) ci = d_assign[myg];

        __pipeline_wait_prior(0);
        __syncthreads();

        // ---- C1: per-thread full dot + weight ----
        float w = 0.f;
        {
            const float4* xr = &s_tile[tid * 16];
            const float4* ar = &s_attn[ci * 16];
            const int xs = tid & 15, as = ci & 15;
            float4 d = make_float4(0.f, 0.f, 0.f, 0.f);
            #pragma unroll
            for (int j = 0; j < 16; j++) {
                const float4 xv = xr[j ^ xs];
                const float4 av = ar[j ^ as];
                d.x += xv.x * av.x;
                d.y += xv.y * av.y;
                d.z += xv.z * av.z;
                d.w += xv.w * av.w;
            }
            const float s = (d.x + d.y) + (d.z + d.w);
            if (myg < c1 && s != 0.f) {
                const float lr = s > 0.f ? s : 0.2f * s;   // leaky_relu(0.2)
                w = __expf(lr);
            }
        }

        // ---- C2: warp accumulates its lanes' genes ----
        {
            const int rbase = wid * 32;
            #pragma unroll 4
            for (int i = 0; i < 32; i++) {
                const float wv = __shfl_sync(0xffffffffu, w, i);
                const int  cig = __shfl_sync(0xffffffffu, ci, i);
                if (wv != 0.f) {                 // warp-uniform branch
                    const int r = rbase + i;
                    const int jj = (lane >> 1) ^ (r & 15);
                    const float2 xv = *(reinterpret_cast<const float2*>(
                        &s_tile[r * 16 + jj]) + (lane & 1));
                    float2* ap =
                        reinterpret_cast<float2*>(wacc + cig * NH) + lane;
                    float2 c = *ap;
                    c.x += wv * xv.x;
                    c.y += wv * xv.y;
                    *ap = c;
                    if (lane == 0) wsum[cig] += wv;
                }
            }
        }
        __syncthreads();   // tile buffer reuse
    }

    // ---- merge per-warp accumulators -> global (spread-address atomics) ----
    for (int i = tid; i < NC * NH; i += BLK) {
        const float s = s_acc[i] + s_acc[NC * NH + i] +
                        s_acc[2 * NC * NH + i] + s_acc[3 * NC * NH + i];
        atomicAdd(&d_outacc[n * NC * NH + i], s);
    }
    for (int i = tid; i < NC; i += BLK) {
        const float s = s_wsum[i] + s_wsum[NC + i] +
                        s_wsum[2 * NC + i] + s_wsum[3 * NC + i];
        atomicAdd(&d_sumw[n * NC + i], s);
    }
}

// ---------------- epilogue --------------------------------------------------

__global__ void k_final(float4* __restrict__ out) {
    int t = blockIdx.x * blockDim.x + threadIdx.x;   // float4 index
    if (t < NN * NC * NH / 4) {
        int ni = t / (NH / 4);
        float s = fmaxf(d_sumw[ni], 1e-10f);
        float4 v = reinterpret_cast<const float4*>(d_outacc)[t];
        v.x /= s; v.y /= s; v.z /= s; v.w /= s;
        out[t] = v;
    }
}

// ---------------- launcher --------------------------------------------------

extern "C" void kernel_launch(void* const* d_in, const int* in_sizes, int n_in,
                              void* d_out, int out_size) {
    const float* x     = (const float*)d_in[0];   // (N, G, H)
    const float* chrom = (const float*)d_in[1];   // (C, G)
    const float* attn  = (const float*)d_in[2];   // (C, H)
    float4* out = (float4*)d_out;                 // (N, C, H)

    (void)in_sizes; (void)n_in; (void)out_size;

    // allow >48KB dynamic smem (idempotent; not a stream op)
    cudaFuncSetAttribute(k_main, cudaFuncAttributeMaxDynamicSharedMemorySize,
                         SMEM_TOTAL);

    // per-gene chromosome assignment + accumulator zeroing
    k_assign<<<NBLKA, BLKA>>>(chrom);

    // tile-phased sequential streaming fused pass
    k_main<<<NN * CHUNKS, BLK, SMEM_TOTAL>>>(x, attn);

    // normalize
    const int nf4 = NN * NC * NH / 4;
    k_final<<<(nf4 + BLK - 1) / BLK, BLK>>>(out);
}

// round 13
// speedup vs baseline: 1.7848x; 1.6877x over previous
#include <cuda_runtime.h>
#include <math.h>

#define NC 23
#define NG 20000
#define NN 64
#define NH 64

#define BLKA 256
#define NBLKA ((NG + BLKA - 1) / BLKA)   // 79

#define SEGS 4
#define BLK 256
#define WARPS (BLK / 32)
#define STREAMS (WARPS * 2)              // 16 half-warp streams per block

// ---- scratch (static device globals; no allocation in kernel_launch) ----
__device__ int   d_offset[NC + 1];
__device__ int   d_blockhist[NBLKA * NC];
__device__ int   d_assign[NG];
__device__ float d_val[NG];
__device__ int2  d_pack[NG];             // (gene idx, gval bits) bucketed
__device__ float d_outacc[NN * NC * NH];
__device__ float d_sumw[NN * NC];
__device__ int   d_arrive;               // static-zero; k_final resets each call

// ---------------- P: fused assign + scatter (one kernel, spin grid-sync) ---

__global__ __launch_bounds__(BLKA)
void k_pre(const float* __restrict__ chrom) {
    __shared__ int s_hist[NC];
    __shared__ int s_off[NC];
    __shared__ int s_base[NC];
    const int tid = threadIdx.x;
    const int bid = blockIdx.x;
    const int g = bid * BLKA + tid;

    // ---- phase 1: per-gene assignment + per-block hist + zeroing ----
    if (tid < NC) s_hist[tid] = 0;
    __syncthreads();

    if (g < NG) {
        int ci = 0;
        float val = 0.f;
        #pragma unroll
        for (int c = 0; c < NC; c++) {
            float v = chrom[c * NG + g];       // coalesced across g
            if (v != 0.f) { ci = c; val = v; }
        }
        d_assign[g] = ci;
        d_val[g] = val;
        atomicAdd(&s_hist[ci], 1);             // smem only
    }

    const int nt = NBLKA * BLKA;
    for (int i = g; i < NN * NC * NH; i += nt)
        d_outacc[i] = 0.f;
    if (g < NN * NC)
        d_sumw[g] = 0.f;

    __syncthreads();
    if (tid < NC) d_blockhist[bid * NC + tid] = s_hist[tid];

    // ---- release: publish phase-1 stores, arrive ----
    __threadfence();
    __syncthreads();
    if (tid == 0) {
        atomicAdd(&d_arrive, 1);
        // spin until all blocks arrived (all 79 blocks co-resident)
        volatile int* va = &d_arrive;
        while (*va < NBLKA) { __nanosleep(64); }
    }
    __syncthreads();
    __threadfence();   // acquire: other blocks' d_assign/d_val/d_blockhist

    // ---- phase 2: scatter; each block derives offsets locally ----
    int tot = 0, pre = 0;
    if (tid < NC) {
        #pragma unroll 4
        for (int b = 0; b < NBLKA; b++) {
            int h = d_blockhist[b * NC + tid];
            tot += h;
            if (b < bid) pre += h;
        }
    }
    if (tid < 32) {
        int v = (tid < NC) ? tot : 0;
        int acc = v;
        #pragma unroll
        for (int d = 1; d < 32; d <<= 1) {
            int u = __shfl_up_sync(0xffffffffu, acc, d);
            if (tid >= d) acc += u;
        }
        if (tid < NC) {
            s_off[tid] = acc - v;
            if (bid == 0) {
                d_offset[tid] = acc - v;
                if (tid == NC - 1) d_offset[NC] = acc;
            }
        }
    }
    __syncthreads();
    if (tid < NC) s_base[tid] = s_off[tid] + pre;
    __syncthreads();

    if (g < NG) {
        int ci = d_assign[g];
        int pos = atomicAdd(&s_base[ci], 1);   // smem-only cursor
        d_pack[pos] = make_int2(g, __float_as_int(d_val[g]));
    }
}

// ---------------- main fused pass (CHAMPION — unchanged) --------------------
// grid: (SEGS, NC, NN). Each half-warp streams genes of chromosome ci for
// batch n. 4-way software pipeline: batch 4 pack loads, then 4 row loads,
// then 4 interleaved shfl/exp chains.

__device__ __forceinline__ void compute_gene(
    const float4 xv, const float v, const float4 a4,
    unsigned hm, float4& acc, float& sumw)
{
    float s = a4.x * xv.x + a4.y * xv.y + a4.z * xv.z + a4.w * xv.w;
    s += __shfl_xor_sync(hm, s, 8);
    s += __shfl_xor_sync(hm, s, 4);
    s += __shfl_xor_sync(hm, s, 2);
    s += __shfl_xor_sync(hm, s, 1);
    float a = s * v;
    float w = 0.f;
    if (a != 0.f) {
        float lr = a > 0.f ? a : 0.2f * a;   // leaky_relu(0.2)
        w = __expf(lr);
    }
    acc.x += w * xv.x;
    acc.y += w * xv.y;
    acc.z += w * xv.z;
    acc.w += w * xv.w;
    sumw += w;
}

__global__ __launch_bounds__(BLK)
void k_main(const float* __restrict__ x, const float* __restrict__ attn) {
    const int seg = blockIdx.x;
    const int ci  = blockIdx.y;
    const int n   = blockIdx.z;

    const int bstart = d_offset[ci];
    const int bend   = d_offset[ci + 1];
    const int cnt    = bend - bstart;
    const int s0 = bstart + (int)((long long)cnt * seg / SEGS);
    const int s1 = bstart + (int)((long long)cnt * (seg + 1) / SEGS);

    const int tid  = threadIdx.x;
    const int wid  = tid >> 5;
    const int lane = tid & 31;
    const int hl   = lane & 15;   // lane within half-warp
    const int half = lane >> 4;
    const unsigned hm = half ? 0xffff0000u : 0x0000ffffu;

    const float4 a4 =
        *reinterpret_cast<const float4*>(attn + ci * NH + hl * 4);

    const float* xbase = x + (long long)n * NG * NH;

    float4 acc = make_float4(0.f, 0.f, 0.f, 0.f);
    float sumw = 0.f;

    const int stream = wid * 2 + half;
    const int step   = STREAMS;          // 16

    int p = s0 + stream;

    // 4-way pipelined: 4 pack loads, 4 front-batched LDG.128, 4 chains
    for (; p + 3 * step < s1; p += 4 * step) {
        const int2 pk0 = d_pack[p];
        const int2 pk1 = d_pack[p + step];
        const int2 pk2 = d_pack[p + 2 * step];
        const int2 pk3 = d_pack[p + 3 * step];
        const float4 x0 = *reinterpret_cast<const float4*>(
            xbase + (long long)pk0.x * NH + hl * 4);
        const float4 x1 = *reinterpret_cast<const float4*>(
            xbase + (long long)pk1.x * NH + hl * 4);
        const float4 x2 = *reinterpret_cast<const float4*>(
            xbase + (long long)pk2.x * NH + hl * 4);
        const float4 x3 = *reinterpret_cast<const float4*>(
            xbase + (long long)pk3.x * NH + hl * 4);
        compute_gene(x0, __int_as_float(pk0.y), a4, hm, acc, sumw);
        compute_gene(x1, __int_as_float(pk1.y), a4, hm, acc, sumw);
        compute_gene(x2, __int_as_float(pk2.y), a4, hm, acc, sumw);
        compute_gene(x3, __int_as_float(pk3.y), a4, hm, acc, sumw);
    }
    for (; p < s1; p += step) {
        const int2 pk = d_pack[p];
        const float4 xv = *reinterpret_cast<const float4*>(
            xbase + (long long)pk.x * NH + hl * 4);
        compute_gene(xv, __int_as_float(pk.y), a4, hm, acc, sumw);
    }

    // combine halves: lanes 0..15 pick up lanes 16..31
    acc.x += __shfl_down_sync(0xffffffffu, acc.x, 16);
    acc.y += __shfl_down_sync(0xffffffffu, acc.y, 16);
    acc.z += __shfl_down_sync(0xffffffffu, acc.z, 16);
    acc.w += __shfl_down_sync(0xffffffffu, acc.w, 16);
    sumw  += __shfl_down_sync(0xffffffffu, sumw, 16);

    // block-level reduction in smem
    __shared__ float s_acc[NH];
    __shared__ float s_sum;
    if (tid < NH) s_acc[tid] = 0.f;
    if (tid == 0) s_sum = 0.f;
    __syncthreads();

    if (lane < 16) {
        atomicAdd(&s_acc[hl * 4 + 0], acc.x);
        atomicAdd(&s_acc[hl * 4 + 1], acc.y);
        atomicAdd(&s_acc[hl * 4 + 2], acc.z);
        atomicAdd(&s_acc[hl * 4 + 3], acc.w);
    }
    if (lane == 0) atomicAdd(&s_sum, sumw);
    __syncthreads();

    const int slot = n * NC + ci;
    float* oacc = d_outacc + (long long)slot * NH;
    if (tid < NH) atomicAdd(&oacc[tid], s_acc[tid]);
    if (tid == 0) atomicAdd(&d_sumw[slot], s_sum);
}

// ---------------- epilogue ---------------------------------------------------

__global__ void k_final(float* __restrict__ out) {
    int t = blockIdx.x * blockDim.x + threadIdx.x;
    if (t == 0) d_arrive = 0;            // reset spin counter for next replay
    if (t < NN * NC * NH) {
        int ni = t / NH;
        float s = d_sumw[ni];
        out[t] = d_outacc[t] / fmaxf(s, 1e-10f);
    }
}

// ---------------- launcher ---------------------------------------------------

extern "C" void kernel_launch(void* const* d_in, const int* in_sizes, int n_in,
                              void* d_out, int out_size) {
    const float* x     = (const float*)d_in[0];   // (N, G, H)
    const float* chrom = (const float*)d_in[1];   // (C, G)
    const float* attn  = (const float*)d_in[2];   // (C, H)
    float* out = (float*)d_out;                   // (N, C, H)

    (void)in_sizes; (void)n_in; (void)out_size;

    // fused bucket-sort preprocessing (single kernel, internal grid sync)
    k_pre<<<NBLKA, BLKA>>>(chrom);

    // fused attention + weighted accumulation (single pass over x)
    dim3 grid(SEGS, NC, NN);
    k_main<<<grid, BLK>>>(x, attn);

    // normalize
    k_final<<<(NN * NC * NH + BLK - 1) / BLK, BLK>>>(out);
}